// round 4
// baseline (speedup 1.0000x reference)
#include <cuda_runtime.h>
#include <cuda_bf16.h>
#include <stdint.h>

#define N_NODES 50000
#define D 256
#define N_EDGES 400000

// Scratch (no allocations allowed — device globals; addresses obtained with
// cudaGetSymbolAddress, a pure lookup, capture-safe).
__device__ float g_h[(size_t)N_NODES * D];     // GEMM output (per layer)
__device__ float g_agg[(size_t)N_NODES * D];   // aggregation output / layer-1 activations
__device__ float g_dinv[N_NODES];              // 1/sqrt(deg)
__device__ float g_enorm[N_EDGES];             // per-edge norm = dinv[src]*dinv[dst]
__device__ int   g_src[N_EDGES];               // decoded int32 edge sources
__device__ int   g_dst[N_EDGES];               // decoded int32 edge destinations
__device__ int   g_is64;                       // 1 if edge_index is int64, else 0

// ---------------------------------------------------------------------------
// dtype detection + index conversion
// edge_index is [2, E]; dtype may be int32 (JAX default, x64 disabled) or int64.
// For int64 little-endian with values < 50000, every odd 32-bit word is 0.
// ---------------------------------------------------------------------------
__global__ void detect_idx_kernel(const unsigned int* __restrict__ ei32) {
    if (threadIdx.x != 0 || blockIdx.x != 0) return;
    int is64 = 1;
    for (int i = 0; i < 64; i++) {
        if (ei32[2 * i + 1] != 0u) { is64 = 0; break; }
    }
    g_is64 = is64;
}

__global__ void convert_idx_kernel(const void* __restrict__ ei, int* __restrict__ srcOut,
                                   int* __restrict__ dstOut) {
    int i = blockIdx.x * blockDim.x + threadIdx.x;
    if (i >= N_EDGES) return;
    if (g_is64) {
        const long long* e = (const long long*)ei;
        srcOut[i] = (int)e[i];
        dstOut[i] = (int)e[i + N_EDGES];
    } else {
        const int* e = (const int*)ei;
        srcOut[i] = e[i];
        dstOut[i] = e[i + N_EDGES];
    }
}

// ---------------------------------------------------------------------------
// degree / norm kernels
// ---------------------------------------------------------------------------
__global__ void init_deg_kernel(float* dinv) {
    int i = blockIdx.x * blockDim.x + threadIdx.x;
    if (i < N_NODES) dinv[i] = 1.0f;  // self-loop contributes 1
}

__global__ void deg_accum_kernel(const int* __restrict__ dst, float* dinv) {
    int i = blockIdx.x * blockDim.x + threadIdx.x;
    if (i < N_EDGES) atomicAdd(&dinv[dst[i]], 1.0f);
}

__global__ void finalize_dinv_kernel(float* dinv) {
    int i = blockIdx.x * blockDim.x + threadIdx.x;
    if (i < N_NODES) dinv[i] = rsqrtf(dinv[i]);  // deg >= 1 always (self-loop)
}

__global__ void edge_norm_kernel(const int* __restrict__ src,
                                 const int* __restrict__ dst,
                                 const float* __restrict__ dinv,
                                 float* __restrict__ enorm) {
    int i = blockIdx.x * blockDim.x + threadIdx.x;
    if (i < N_EDGES) enorm[i] = dinv[src[i]] * dinv[dst[i]];
}

// ---------------------------------------------------------------------------
// SGEMM: C[M x 256] = A[M x 256] @ B[256 x 256], fp32, row-major
// 128x128 block tile, BK=16, 256 threads, 8x8 per-thread microtile.
// ---------------------------------------------------------------------------
#define BM 128
#define BN 128
#define BK 16
#define TM 8
#define TN 8

__global__ __launch_bounds__(256) void sgemm_kernel(
    const float* __restrict__ A, const float* __restrict__ B,
    float* __restrict__ C, int M) {
    __shared__ float As[BK][BM];
    __shared__ float Bs[BK][BN];

    const int tid = threadIdx.x;
    const int tcol = tid & 15;   // 0..15
    const int trow = tid >> 4;   // 0..15
    const int rowBase = blockIdx.x * BM;
    const int colBase = blockIdx.y * BN;

    float acc[TM][TN];
#pragma unroll
    for (int i = 0; i < TM; i++)
#pragma unroll
        for (int j = 0; j < TN; j++) acc[i][j] = 0.0f;

    for (int k0 = 0; k0 < D; k0 += BK) {
        // Load A tile (128 rows x 16 cols) — 512 float4, 2 per thread, transpose into As
#pragma unroll
        for (int i = 0; i < 2; i++) {
            int q = tid * 2 + i;
            int ar = q >> 2;             // row within tile 0..127
            int ak = (q & 3) << 2;       // k within tile {0,4,8,12}
            float4 av = make_float4(0.f, 0.f, 0.f, 0.f);
            int grow = rowBase + ar;
            if (grow < M)
                av = *(const float4*)(A + (size_t)grow * D + k0 + ak);
            As[ak + 0][ar] = av.x;
            As[ak + 1][ar] = av.y;
            As[ak + 2][ar] = av.z;
            As[ak + 3][ar] = av.w;

            // Load B tile (16 rows x 128 cols) — 512 float4, 2 per thread
            int br = q >> 5;             // 0..15
            int bc = (q & 31) << 2;      // 0..124
            float4 bv = *(const float4*)(B + (size_t)(k0 + br) * D + colBase + bc);
            *(float4*)&Bs[br][bc] = bv;
        }
        __syncthreads();

#pragma unroll
        for (int kk = 0; kk < BK; kk++) {
            float ra[TM], rb[TN];
#pragma unroll
            for (int i = 0; i < TM; i++) ra[i] = As[kk][trow * TM + i];
#pragma unroll
            for (int j = 0; j < TN; j++) rb[j] = Bs[kk][tcol * TN + j];
#pragma unroll
            for (int i = 0; i < TM; i++)
#pragma unroll
                for (int j = 0; j < TN; j++) acc[i][j] += ra[i] * rb[j];
        }
        __syncthreads();
    }

#pragma unroll
    for (int i = 0; i < TM; i++) {
        int grow = rowBase + trow * TM + i;
        if (grow < M) {
#pragma unroll
            for (int j = 0; j < TN; j += 4) {
                *(float4*)(C + (size_t)grow * D + colBase + tcol * TN + j) =
                    make_float4(acc[i][j], acc[i][j + 1], acc[i][j + 2], acc[i][j + 3]);
            }
        }
    }
}

// ---------------------------------------------------------------------------
// Self-loop init: out[i,:] = h[i,:] * dinv[i]^2   (one float4 per thread)
// ---------------------------------------------------------------------------
__global__ void self_init_kernel(const float* __restrict__ h,
                                 const float* __restrict__ dinv,
                                 float* __restrict__ out) {
    int i = blockIdx.x * blockDim.x + threadIdx.x;  // over N*64 float4
    if (i >= N_NODES * (D / 4)) return;
    int node = i >> 6;
    float w = dinv[node];
    w = w * w;
    float4 v = ((const float4*)h)[i];
    ((float4*)out)[i] = make_float4(v.x * w, v.y * w, v.z * w, v.w * w);
}

// ---------------------------------------------------------------------------
// Edge scatter: one warp per edge. Gather h[src,:]*enorm, atomicAdd into out[dst,:]
// ---------------------------------------------------------------------------
__global__ void scatter_kernel(const float* __restrict__ h,
                               const float* __restrict__ enorm,
                               const int* __restrict__ src,
                               const int* __restrict__ dst,
                               float* __restrict__ out) {
    int w = (blockIdx.x * blockDim.x + threadIdx.x) >> 5;
    if (w >= N_EDGES) return;
    int lane = threadIdx.x & 31;
    int s = __ldg(&src[w]);
    int t = __ldg(&dst[w]);
    float nm = __ldg(&enorm[w]);
    const float4* hp = (const float4*)(h + (size_t)s * D);
    float* op = out + (size_t)t * D;
    float4 v0 = hp[lane];
    float4 v1 = hp[lane + 32];
    int c0 = lane * 4;
    atomicAdd(op + c0 + 0, v0.x * nm);
    atomicAdd(op + c0 + 1, v0.y * nm);
    atomicAdd(op + c0 + 2, v0.z * nm);
    atomicAdd(op + c0 + 3, v0.w * nm);
    int c1 = 128 + lane * 4;
    atomicAdd(op + c1 + 0, v1.x * nm);
    atomicAdd(op + c1 + 1, v1.y * nm);
    atomicAdd(op + c1 + 2, v1.z * nm);
    atomicAdd(op + c1 + 3, v1.w * nm);
}

// ---------------------------------------------------------------------------
// out = relu(out + b), in place (one float4 per thread)
// ---------------------------------------------------------------------------
__global__ void bias_relu_kernel(float* __restrict__ out, const float* __restrict__ b) {
    int i = blockIdx.x * blockDim.x + threadIdx.x;
    if (i >= N_NODES * (D / 4)) return;
    int col4 = (i & 63) * 4;
    float4 bb = *(const float4*)(b + col4);
    float4 v = ((float4*)out)[i];
    v.x = fmaxf(v.x + bb.x, 0.f);
    v.y = fmaxf(v.y + bb.y, 0.f);
    v.z = fmaxf(v.z + bb.z, 0.f);
    v.w = fmaxf(v.w + bb.w, 0.f);
    ((float4*)out)[i] = v;
}

// ---------------------------------------------------------------------------
// Launch
// ---------------------------------------------------------------------------
extern "C" void kernel_launch(void* const* d_in, const int* in_sizes, int n_in,
                              void* d_out, int out_size) {
    const float* x = (const float*)d_in[0];
    const void* ei = d_in[1];  // [2, E] — int32 or int64, detected on device
    const float* W1 = (const float*)d_in[2];
    const float* b1 = (const float*)d_in[3];
    const float* W2 = (const float*)d_in[4];
    const float* b2 = (const float*)d_in[5];
    float* out = (float*)d_out;

    // Device addresses of the __device__ scratch globals (pure lookup).
    float *h, *agg, *dinv, *enorm;
    int *srcI, *dstI;
    cudaGetSymbolAddress((void**)&h, g_h);
    cudaGetSymbolAddress((void**)&agg, g_agg);
    cudaGetSymbolAddress((void**)&dinv, g_dinv);
    cudaGetSymbolAddress((void**)&enorm, g_enorm);
    cudaGetSymbolAddress((void**)&srcI, g_src);
    cudaGetSymbolAddress((void**)&dstI, g_dst);

    const int TPB = 256;
    const int nThreadsElem = N_NODES * (D / 4);           // 3.2M
    const int gElem = (nThreadsElem + TPB - 1) / TPB;
    const int gN = (N_NODES + TPB - 1) / TPB;
    const int gE = (N_EDGES + TPB - 1) / TPB;
    const long long scatterThreads = (long long)N_EDGES * 32;
    const int gScatter = (int)((scatterThreads + TPB - 1) / TPB);
    dim3 gGemm((N_NODES + BM - 1) / BM, D / BN);

    // decode edge indices (dtype-agnostic), then degrees + per-edge norms
    detect_idx_kernel<<<1, 32>>>((const unsigned int*)ei);
    convert_idx_kernel<<<gE, TPB>>>(ei, srcI, dstI);
    init_deg_kernel<<<gN, TPB>>>(dinv);
    deg_accum_kernel<<<gE, TPB>>>(dstI, dinv);
    finalize_dinv_kernel<<<gN, TPB>>>(dinv);
    edge_norm_kernel<<<gE, TPB>>>(srcI, dstI, dinv, enorm);

    // ---- layer 1 ----
    sgemm_kernel<<<gGemm, TPB>>>(x, W1, h, N_NODES);
    self_init_kernel<<<gElem, TPB>>>(h, dinv, agg);
    scatter_kernel<<<gScatter, TPB>>>(h, enorm, srcI, dstI, agg);
    bias_relu_kernel<<<gElem, TPB>>>(agg, b1);

    // ---- layer 2 ----
    sgemm_kernel<<<gGemm, TPB>>>(agg, W2, h, N_NODES);
    self_init_kernel<<<gElem, TPB>>>(h, dinv, out);
    scatter_kernel<<<gScatter, TPB>>>(h, enorm, srcI, dstI, out);
    bias_relu_kernel<<<gElem, TPB>>>(out, b2);
}

// round 5
// speedup vs baseline: 1.7597x; 1.7597x over previous
#include <cuda_runtime.h>
#include <cuda_bf16.h>
#include <stdint.h>

#define N_NODES 50000
#define D 256
#define N_EDGES 400000

// Scratch — device globals (no allocations allowed).
__device__ float g_h[(size_t)N_NODES * D];     // GEMM output (per layer)
__device__ float g_agg[(size_t)N_NODES * D];   // layer-1 activations
__device__ float g_dinv[N_NODES];              // 1/sqrt(deg) (deg incl. self-loop)
__device__ int   g_cnt[N_NODES];               // in-edge counts (excl. self-loop)
__device__ int   g_cursor[N_NODES];            // bucket-fill cursors
__device__ int   g_rowstart[N_NODES + 1];      // CSR row offsets (by dst)
__device__ int   g_csr_src[N_EDGES];           // CSR: source node per in-edge
__device__ float g_csr_w[N_EDGES];             // CSR: dinv[src]*dinv[dst] per in-edge
__device__ int   g_src[N_EDGES];               // decoded int32 edge sources
__device__ int   g_dst[N_EDGES];               // decoded int32 edge destinations
__device__ int   g_is64;                       // 1 if edge_index is int64

// ---------------------------------------------------------------------------
// dtype detection + index conversion (edge_index may be int32 or int64)
// ---------------------------------------------------------------------------
__global__ void detect_idx_kernel(const unsigned int* __restrict__ ei32) {
    if (threadIdx.x != 0 || blockIdx.x != 0) return;
    int is64 = 1;
    for (int i = 0; i < 64; i++)
        if (ei32[2 * i + 1] != 0u) { is64 = 0; break; }
    g_is64 = is64;
}

__global__ void convert_idx_kernel(const void* __restrict__ ei, int* __restrict__ srcOut,
                                   int* __restrict__ dstOut) {
    int i = blockIdx.x * blockDim.x + threadIdx.x;
    if (i >= N_EDGES) return;
    if (g_is64) {
        const long long* e = (const long long*)ei;
        srcOut[i] = (int)e[i];
        dstOut[i] = (int)e[i + N_EDGES];
    } else {
        const int* e = (const int*)ei;
        srcOut[i] = e[i];
        dstOut[i] = e[i + N_EDGES];
    }
}

// ---------------------------------------------------------------------------
// CSR build: count -> scan -> dinv -> fill
// ---------------------------------------------------------------------------
__global__ void zero_cnt_kernel(int* cnt, int* cursor) {
    int i = blockIdx.x * blockDim.x + threadIdx.x;
    if (i < N_NODES) { cnt[i] = 0; cursor[i] = 0; }
}

__global__ void count_kernel(const int* __restrict__ dst, int* cnt) {
    int i = blockIdx.x * blockDim.x + threadIdx.x;
    if (i < N_EDGES) atomicAdd(&cnt[dst[i]], 1);
}

// Single-block exclusive prefix scan over 50000 counts (1024 threads).
__global__ __launch_bounds__(1024) void scan_kernel(const int* __restrict__ cnt,
                                                    int* __restrict__ rowstart) {
    __shared__ int sums[1024];
    const int tid = threadIdx.x;
    const int CH = (N_NODES + 1023) / 1024;  // 49
    const int base = tid * CH;
    int s = 0;
    for (int i = 0; i < CH; i++) {
        int idx = base + i;
        if (idx < N_NODES) s += cnt[idx];
    }
    sums[tid] = s;
    __syncthreads();
    for (int off = 1; off < 1024; off <<= 1) {
        int u = (tid >= off) ? sums[tid - off] : 0;
        __syncthreads();
        sums[tid] += u;
        __syncthreads();
    }
    int run = (tid == 0) ? 0 : sums[tid - 1];
    for (int i = 0; i < CH; i++) {
        int idx = base + i;
        if (idx < N_NODES) { rowstart[idx] = run; run += cnt[idx]; }
    }
    if (tid == 1023) rowstart[N_NODES] = sums[1023];
}

__global__ void dinv_kernel(const int* __restrict__ cnt, float* dinv) {
    int i = blockIdx.x * blockDim.x + threadIdx.x;
    if (i < N_NODES) dinv[i] = rsqrtf((float)(cnt[i] + 1));  // +1 self-loop
}

__global__ void fill_kernel(const int* __restrict__ src, const int* __restrict__ dst,
                            const int* __restrict__ rowstart, int* cursor,
                            const float* __restrict__ dinv,
                            int* __restrict__ csr_src, float* __restrict__ csr_w) {
    int i = blockIdx.x * blockDim.x + threadIdx.x;
    if (i >= N_EDGES) return;
    int s = src[i], t = dst[i];
    int pos = rowstart[t] + atomicAdd(&cursor[t], 1);
    csr_src[pos] = s;
    csr_w[pos] = dinv[s] * dinv[t];
}

// ---------------------------------------------------------------------------
// SGEMM: C[M x 256] = A[M x 256] @ B[256 x 256], fp32, row-major
// 128x128 block tile, BK=16, 256 threads, 8x8 per-thread microtile.
// ---------------------------------------------------------------------------
#define BM 128
#define BN 128
#define BK 16
#define TM 8
#define TN 8

__global__ __launch_bounds__(256) void sgemm_kernel(
    const float* __restrict__ A, const float* __restrict__ B,
    float* __restrict__ C, int M) {
    __shared__ float As[BK][BM];
    __shared__ float Bs[BK][BN];

    const int tid = threadIdx.x;
    const int tcol = tid & 15;
    const int trow = tid >> 4;
    const int rowBase = blockIdx.x * BM;
    const int colBase = blockIdx.y * BN;

    float acc[TM][TN];
#pragma unroll
    for (int i = 0; i < TM; i++)
#pragma unroll
        for (int j = 0; j < TN; j++) acc[i][j] = 0.0f;

    for (int k0 = 0; k0 < D; k0 += BK) {
#pragma unroll
        for (int i = 0; i < 2; i++) {
            int q = tid * 2 + i;
            int ar = q >> 2;
            int ak = (q & 3) << 2;
            float4 av = make_float4(0.f, 0.f, 0.f, 0.f);
            int grow = rowBase + ar;
            if (grow < M)
                av = *(const float4*)(A + (size_t)grow * D + k0 + ak);
            As[ak + 0][ar] = av.x;
            As[ak + 1][ar] = av.y;
            As[ak + 2][ar] = av.z;
            As[ak + 3][ar] = av.w;

            int br = q >> 5;
            int bc = (q & 31) << 2;
            float4 bv = *(const float4*)(B + (size_t)(k0 + br) * D + colBase + bc);
            *(float4*)&Bs[br][bc] = bv;
        }
        __syncthreads();

#pragma unroll
        for (int kk = 0; kk < BK; kk++) {
            float ra[TM], rb[TN];
#pragma unroll
            for (int i = 0; i < TM; i++) ra[i] = As[kk][trow * TM + i];
#pragma unroll
            for (int j = 0; j < TN; j++) rb[j] = Bs[kk][tcol * TN + j];
#pragma unroll
            for (int i = 0; i < TM; i++)
#pragma unroll
                for (int j = 0; j < TN; j++) acc[i][j] += ra[i] * rb[j];
        }
        __syncthreads();
    }

#pragma unroll
    for (int i = 0; i < TM; i++) {
        int grow = rowBase + trow * TM + i;
        if (grow < M) {
#pragma unroll
            for (int j = 0; j < TN; j += 4) {
                *(float4*)(C + (size_t)grow * D + colBase + tcol * TN + j) =
                    make_float4(acc[i][j], acc[i][j + 1], acc[i][j + 2], acc[i][j + 3]);
            }
        }
    }
}

// ---------------------------------------------------------------------------
// Fused gather: warp-per-node.
// out[n,:] = relu( h[n,:]*dinv[n]^2 + sum_in-edges h[src,:]*w + b )
// ---------------------------------------------------------------------------
__global__ __launch_bounds__(256) void gather_kernel(
    const float* __restrict__ h,
    const int* __restrict__ rowstart,
    const int* __restrict__ csr_src,
    const float* __restrict__ csr_w,
    const float* __restrict__ dinv,
    const float* __restrict__ bias,
    float* __restrict__ out) {
    int node = (blockIdx.x * blockDim.x + threadIdx.x) >> 5;
    if (node >= N_NODES) return;
    int lane = threadIdx.x & 31;

    // self-loop term
    float dv = dinv[node];
    float w0 = dv * dv;
    const float4* selfp = (const float4*)(h + (size_t)node * D);
    float4 a0 = selfp[lane];
    float4 a1 = selfp[lane + 32];
    a0.x *= w0; a0.y *= w0; a0.z *= w0; a0.w *= w0;
    a1.x *= w0; a1.y *= w0; a1.z *= w0; a1.w *= w0;

    int beg = rowstart[node];
    int end = rowstart[node + 1];
    for (int j = beg; j < end; j++) {
        int s = __ldg(&csr_src[j]);      // broadcast (all lanes same addr)
        float w = __ldg(&csr_w[j]);
        const float4* sp = (const float4*)(h + (size_t)s * D);
        float4 v0 = sp[lane];
        float4 v1 = sp[lane + 32];
        a0.x = fmaf(v0.x, w, a0.x); a0.y = fmaf(v0.y, w, a0.y);
        a0.z = fmaf(v0.z, w, a0.z); a0.w = fmaf(v0.w, w, a0.w);
        a1.x = fmaf(v1.x, w, a1.x); a1.y = fmaf(v1.y, w, a1.y);
        a1.z = fmaf(v1.z, w, a1.z); a1.w = fmaf(v1.w, w, a1.w);
    }

    const float4* b4 = (const float4*)bias;
    float4 bb0 = b4[lane];
    float4 bb1 = b4[lane + 32];
    a0.x = fmaxf(a0.x + bb0.x, 0.f); a0.y = fmaxf(a0.y + bb0.y, 0.f);
    a0.z = fmaxf(a0.z + bb0.z, 0.f); a0.w = fmaxf(a0.w + bb0.w, 0.f);
    a1.x = fmaxf(a1.x + bb1.x, 0.f); a1.y = fmaxf(a1.y + bb1.y, 0.f);
    a1.z = fmaxf(a1.z + bb1.z, 0.f); a1.w = fmaxf(a1.w + bb1.w, 0.f);

    float4* op = (float4*)(out + (size_t)node * D);
    op[lane] = a0;
    op[lane + 32] = a1;
}

// ---------------------------------------------------------------------------
// Launch
// ---------------------------------------------------------------------------
extern "C" void kernel_launch(void* const* d_in, const int* in_sizes, int n_in,
                              void* d_out, int out_size) {
    const float* x = (const float*)d_in[0];
    const void* ei = d_in[1];  // [2, E] — int32 or int64, detected on device
    const float* W1 = (const float*)d_in[2];
    const float* b1 = (const float*)d_in[3];
    const float* W2 = (const float*)d_in[4];
    const float* b2 = (const float*)d_in[5];
    float* out = (float*)d_out;

    float *h, *agg, *dinv, *csr_w;
    int *srcI, *dstI, *cnt, *cursor, *rowstart, *csr_src;
    cudaGetSymbolAddress((void**)&h, g_h);
    cudaGetSymbolAddress((void**)&agg, g_agg);
    cudaGetSymbolAddress((void**)&dinv, g_dinv);
    cudaGetSymbolAddress((void**)&cnt, g_cnt);
    cudaGetSymbolAddress((void**)&cursor, g_cursor);
    cudaGetSymbolAddress((void**)&rowstart, g_rowstart);
    cudaGetSymbolAddress((void**)&csr_src, g_csr_src);
    cudaGetSymbolAddress((void**)&csr_w, g_csr_w);
    cudaGetSymbolAddress((void**)&srcI, g_src);
    cudaGetSymbolAddress((void**)&dstI, g_dst);

    const int TPB = 256;
    const int gN = (N_NODES + TPB - 1) / TPB;
    const int gE = (N_EDGES + TPB - 1) / TPB;
    const int gGather = (int)(((long long)N_NODES * 32 + TPB - 1) / TPB);
    dim3 gGemm((N_NODES + BM - 1) / BM, D / BN);

    // ---- prep: decode indices, build CSR by destination ----
    detect_idx_kernel<<<1, 32>>>((const unsigned int*)ei);
    convert_idx_kernel<<<gE, TPB>>>(ei, srcI, dstI);
    zero_cnt_kernel<<<gN, TPB>>>(cnt, cursor);
    count_kernel<<<gE, TPB>>>(dstI, cnt);
    scan_kernel<<<1, 1024>>>(cnt, rowstart);
    dinv_kernel<<<gN, TPB>>>(cnt, dinv);
    fill_kernel<<<gE, TPB>>>(srcI, dstI, rowstart, cursor, dinv, csr_src, csr_w);

    // ---- layer 1 ----
    sgemm_kernel<<<gGemm, TPB>>>(x, W1, h, N_NODES);
    gather_kernel<<<gGather, TPB>>>(h, rowstart, csr_src, csr_w, dinv, b1, agg);

    // ---- layer 2 ----
    sgemm_kernel<<<gGemm, TPB>>>(agg, W2, h, N_NODES);
    gather_kernel<<<gGather, TPB>>>(h, rowstart, csr_src, csr_w, dinv, b2, out);
}

// round 6
// speedup vs baseline: 2.0048x; 1.1393x over previous
#include <cuda_runtime.h>
#include <cuda_bf16.h>
#include <stdint.h>

#define N_NODES 50000
#define D 256
#define N_EDGES 400000

// Scratch — device globals (no allocations allowed).
__device__ float g_h[(size_t)N_NODES * D];     // GEMM output (per layer)
__device__ float g_agg[(size_t)N_NODES * D];   // layer-1 activations
__device__ float g_dinv[N_NODES];              // 1/sqrt(deg) (deg incl. self-loop)
__device__ int   g_cnt[N_NODES];               // in-edge counts (excl. self-loop)
__device__ int   g_cursor[N_NODES];            // bucket-fill cursors
__device__ int   g_rowstart[N_NODES + 1];      // CSR row offsets (by dst)
__device__ int   g_csr_src[N_EDGES];           // CSR: source node per in-edge
__device__ float g_csr_w[N_EDGES];             // CSR: dinv[src]*dinv[dst] per in-edge
__device__ int   g_src[N_EDGES];               // decoded int32 edge sources
__device__ int   g_dst[N_EDGES];               // decoded int32 edge destinations
__device__ int   g_is64;                       // 1 if edge_index is int64

// ---------------------------------------------------------------------------
// dtype detection + index conversion (edge_index may be int32 or int64)
// ---------------------------------------------------------------------------
__global__ void detect_idx_kernel(const unsigned int* __restrict__ ei32) {
    if (threadIdx.x != 0 || blockIdx.x != 0) return;
    int is64 = 1;
    for (int i = 0; i < 64; i++)
        if (ei32[2 * i + 1] != 0u) { is64 = 0; break; }
    g_is64 = is64;
}

__global__ void convert_idx_kernel(const void* __restrict__ ei, int* __restrict__ srcOut,
                                   int* __restrict__ dstOut) {
    int i = blockIdx.x * blockDim.x + threadIdx.x;
    if (i >= N_EDGES) return;
    if (g_is64) {
        const long long* e = (const long long*)ei;
        srcOut[i] = (int)e[i];
        dstOut[i] = (int)e[i + N_EDGES];
    } else {
        const int* e = (const int*)ei;
        srcOut[i] = e[i];
        dstOut[i] = e[i + N_EDGES];
    }
}

// ---------------------------------------------------------------------------
// CSR build: count -> scan -> dinv -> fill
// ---------------------------------------------------------------------------
__global__ void zero_cnt_kernel(int* cnt, int* cursor) {
    int i = blockIdx.x * blockDim.x + threadIdx.x;
    if (i < N_NODES) { cnt[i] = 0; cursor[i] = 0; }
}

__global__ void count_kernel(const int* __restrict__ dst, int* cnt) {
    int i = blockIdx.x * blockDim.x + threadIdx.x;
    if (i < N_EDGES) atomicAdd(&cnt[dst[i]], 1);
}

// Single-block exclusive prefix scan over 50000 counts (1024 threads).
__global__ __launch_bounds__(1024) void scan_kernel(const int* __restrict__ cnt,
                                                    int* __restrict__ rowstart) {
    __shared__ int sums[1024];
    const int tid = threadIdx.x;
    const int CH = (N_NODES + 1023) / 1024;  // 49
    const int base = tid * CH;
    int s = 0;
    for (int i = 0; i < CH; i++) {
        int idx = base + i;
        if (idx < N_NODES) s += cnt[idx];
    }
    sums[tid] = s;
    __syncthreads();
    for (int off = 1; off < 1024; off <<= 1) {
        int u = (tid >= off) ? sums[tid - off] : 0;
        __syncthreads();
        sums[tid] += u;
        __syncthreads();
    }
    int run = (tid == 0) ? 0 : sums[tid - 1];
    for (int i = 0; i < CH; i++) {
        int idx = base + i;
        if (idx < N_NODES) { rowstart[idx] = run; run += cnt[idx]; }
    }
    if (tid == 1023) rowstart[N_NODES] = sums[1023];
}

__global__ void dinv_kernel(const int* __restrict__ cnt, float* dinv) {
    int i = blockIdx.x * blockDim.x + threadIdx.x;
    if (i < N_NODES) dinv[i] = rsqrtf((float)(cnt[i] + 1));  // +1 self-loop
}

__global__ void fill_kernel(const int* __restrict__ src, const int* __restrict__ dst,
                            const int* __restrict__ rowstart, int* cursor,
                            const float* __restrict__ dinv,
                            int* __restrict__ csr_src, float* __restrict__ csr_w) {
    int i = blockIdx.x * blockDim.x + threadIdx.x;
    if (i >= N_EDGES) return;
    int s = src[i], t = dst[i];
    int pos = rowstart[t] + atomicAdd(&cursor[t], 1);
    csr_src[pos] = s;
    csr_w[pos] = dinv[s] * dinv[t];
}

// ---------------------------------------------------------------------------
// TF32 split-precision tensor-core GEMM.
// C[M x 256] = A[M x 256] @ B[256 x 256], fp32 in/out, row-major.
// Split A = Ah + Al, B = Bh + Bl (tf32 each); C ~= AhBh + AhBl + AlBh.
// Block tile 128x64, 8 warps, warp tile 32x32, mma.sync m16n8k8.
// ---------------------------------------------------------------------------
#define BM 128
#define BN 64
#define BK 16

__device__ __forceinline__ void split_tf32(float x, uint32_t& hi, uint32_t& lo) {
    uint32_t h;
    asm("cvt.rna.tf32.f32 %0, %1;" : "=r"(h) : "f"(x));
    float hf = __uint_as_float(h);
    uint32_t l;
    asm("cvt.rna.tf32.f32 %0, %1;" : "=r"(l) : "f"(x - hf));
    hi = h; lo = l;
}

__device__ __forceinline__ void mma_tf32(float* c, const uint32_t* a, const uint32_t* b) {
    asm volatile(
        "mma.sync.aligned.m16n8k8.row.col.f32.tf32.tf32.f32 "
        "{%0,%1,%2,%3}, {%4,%5,%6,%7}, {%8,%9}, {%0,%1,%2,%3};"
        : "+f"(c[0]), "+f"(c[1]), "+f"(c[2]), "+f"(c[3])
        : "r"(a[0]), "r"(a[1]), "r"(a[2]), "r"(a[3]), "r"(b[0]), "r"(b[1]));
}

__global__ __launch_bounds__(256) void tgemm_kernel(
    const float* __restrict__ A, const float* __restrict__ B,
    float* __restrict__ C, int M) {
    __shared__ float As[BK][BM + 4];   // [k][m], padded
    __shared__ float Bs[BK][BN + 4];   // [k][n], padded

    const int tid = threadIdx.x;
    const int lane = tid & 31;
    const int wid = tid >> 5;
    const int warpM = wid & 3;          // 0..3 -> m offset 32*warpM
    const int warpN = wid >> 2;         // 0..1 -> n offset 32*warpN
    const int g = lane >> 2;            // groupID 0..7
    const int t = lane & 3;             // threadInGroup 0..3
    const int rowBase = blockIdx.x * BM;
    const int colBase = blockIdx.y * BN;

    float c[2][4][4];                   // [mTile][nTile][reg]
#pragma unroll
    for (int mt = 0; mt < 2; mt++)
#pragma unroll
        for (int nt = 0; nt < 4; nt++)
#pragma unroll
            for (int r = 0; r < 4; r++) c[mt][nt][r] = 0.0f;

    for (int k0 = 0; k0 < D; k0 += BK) {
        // Load A tile (128 x 16), transpose into As[k][m]: 512 float4, 2/thread
#pragma unroll
        for (int i = 0; i < 2; i++) {
            int q = tid * 2 + i;
            int ar = q >> 2;
            int ak = (q & 3) << 2;
            float4 av = make_float4(0.f, 0.f, 0.f, 0.f);
            int grow = rowBase + ar;
            if (grow < M)
                av = *(const float4*)(A + (size_t)grow * D + k0 + ak);
            As[ak + 0][ar] = av.x;
            As[ak + 1][ar] = av.y;
            As[ak + 2][ar] = av.z;
            As[ak + 3][ar] = av.w;
        }
        // Load B tile (16 x 64): 256 float4, 1/thread
        {
            int br = tid >> 4;            // 0..15
            int bc = (tid & 15) << 2;     // 0..60
            float4 bv = *(const float4*)(B + (size_t)(k0 + br) * D + colBase + bc);
            Bs[br][bc + 0] = bv.x;
            Bs[br][bc + 1] = bv.y;
            Bs[br][bc + 2] = bv.z;
            Bs[br][bc + 3] = bv.w;
        }
        __syncthreads();

#pragma unroll
        for (int ks = 0; ks < BK; ks += 8) {
            // A fragments (2 m-tiles), split hi/lo
            uint32_t ah[2][4], al[2][4];
#pragma unroll
            for (int mt = 0; mt < 2; mt++) {
                int m0 = warpM * 32 + mt * 16;
                split_tf32(As[ks + t][m0 + g],          ah[mt][0], al[mt][0]);
                split_tf32(As[ks + t][m0 + g + 8],      ah[mt][1], al[mt][1]);
                split_tf32(As[ks + t + 4][m0 + g],      ah[mt][2], al[mt][2]);
                split_tf32(As[ks + t + 4][m0 + g + 8],  ah[mt][3], al[mt][3]);
            }
            // B fragments (4 n-tiles), split hi/lo
            uint32_t bh[4][2], bl[4][2];
#pragma unroll
            for (int nt = 0; nt < 4; nt++) {
                int n0 = warpN * 32 + nt * 8;
                split_tf32(Bs[ks + t][n0 + g],      bh[nt][0], bl[nt][0]);
                split_tf32(Bs[ks + t + 4][n0 + g],  bh[nt][1], bl[nt][1]);
            }
#pragma unroll
            for (int mt = 0; mt < 2; mt++)
#pragma unroll
                for (int nt = 0; nt < 4; nt++) {
                    mma_tf32(c[mt][nt], ah[mt], bh[nt]);
                    mma_tf32(c[mt][nt], ah[mt], bl[nt]);
                    mma_tf32(c[mt][nt], al[mt], bh[nt]);
                }
        }
        __syncthreads();
    }

    // Epilogue: each frag -> two float2 stores
#pragma unroll
    for (int mt = 0; mt < 2; mt++) {
#pragma unroll
        for (int nt = 0; nt < 4; nt++) {
            int row0 = rowBase + warpM * 32 + mt * 16 + g;
            int col = colBase + warpN * 32 + nt * 8 + t * 2;
            if (row0 < M)
                *(float2*)(C + (size_t)row0 * D + col) =
                    make_float2(c[mt][nt][0], c[mt][nt][1]);
            if (row0 + 8 < M)
                *(float2*)(C + (size_t)(row0 + 8) * D + col) =
                    make_float2(c[mt][nt][2], c[mt][nt][3]);
        }
    }
}

// ---------------------------------------------------------------------------
// Fused gather: warp-per-node.
// out[n,:] = relu( h[n,:]*dinv[n]^2 + sum_in-edges h[src,:]*w + b )
// ---------------------------------------------------------------------------
__global__ __launch_bounds__(256) void gather_kernel(
    const float* __restrict__ h,
    const int* __restrict__ rowstart,
    const int* __restrict__ csr_src,
    const float* __restrict__ csr_w,
    const float* __restrict__ dinv,
    const float* __restrict__ bias,
    float* __restrict__ out) {
    int node = (blockIdx.x * blockDim.x + threadIdx.x) >> 5;
    if (node >= N_NODES) return;
    int lane = threadIdx.x & 31;

    float dv = dinv[node];
    float w0 = dv * dv;
    const float4* selfp = (const float4*)(h + (size_t)node * D);
    float4 a0 = selfp[lane];
    float4 a1 = selfp[lane + 32];
    a0.x *= w0; a0.y *= w0; a0.z *= w0; a0.w *= w0;
    a1.x *= w0; a1.y *= w0; a1.z *= w0; a1.w *= w0;

    int beg = rowstart[node];
    int end = rowstart[node + 1];
    for (int j = beg; j < end; j++) {
        int s = __ldg(&csr_src[j]);
        float w = __ldg(&csr_w[j]);
        const float4* sp = (const float4*)(h + (size_t)s * D);
        float4 v0 = sp[lane];
        float4 v1 = sp[lane + 32];
        a0.x = fmaf(v0.x, w, a0.x); a0.y = fmaf(v0.y, w, a0.y);
        a0.z = fmaf(v0.z, w, a0.z); a0.w = fmaf(v0.w, w, a0.w);
        a1.x = fmaf(v1.x, w, a1.x); a1.y = fmaf(v1.y, w, a1.y);
        a1.z = fmaf(v1.z, w, a1.z); a1.w = fmaf(v1.w, w, a1.w);
    }

    const float4* b4 = (const float4*)bias;
    float4 bb0 = b4[lane];
    float4 bb1 = b4[lane + 32];
    a0.x = fmaxf(a0.x + bb0.x, 0.f); a0.y = fmaxf(a0.y + bb0.y, 0.f);
    a0.z = fmaxf(a0.z + bb0.z, 0.f); a0.w = fmaxf(a0.w + bb0.w, 0.f);
    a1.x = fmaxf(a1.x + bb1.x, 0.f); a1.y = fmaxf(a1.y + bb1.y, 0.f);
    a1.z = fmaxf(a1.z + bb1.z, 0.f); a1.w = fmaxf(a1.w + bb1.w, 0.f);

    float4* op = (float4*)(out + (size_t)node * D);
    op[lane] = a0;
    op[lane + 32] = a1;
}

// ---------------------------------------------------------------------------
// Launch
// ---------------------------------------------------------------------------
extern "C" void kernel_launch(void* const* d_in, const int* in_sizes, int n_in,
                              void* d_out, int out_size) {
    const float* x = (const float*)d_in[0];
    const void* ei = d_in[1];  // [2, E] — int32 or int64, detected on device
    const float* W1 = (const float*)d_in[2];
    const float* b1 = (const float*)d_in[3];
    const float* W2 = (const float*)d_in[4];
    const float* b2 = (const float*)d_in[5];
    float* out = (float*)d_out;

    float *h, *agg, *dinv, *csr_w;
    int *srcI, *dstI, *cnt, *cursor, *rowstart, *csr_src;
    cudaGetSymbolAddress((void**)&h, g_h);
    cudaGetSymbolAddress((void**)&agg, g_agg);
    cudaGetSymbolAddress((void**)&dinv, g_dinv);
    cudaGetSymbolAddress((void**)&cnt, g_cnt);
    cudaGetSymbolAddress((void**)&cursor, g_cursor);
    cudaGetSymbolAddress((void**)&rowstart, g_rowstart);
    cudaGetSymbolAddress((void**)&csr_src, g_csr_src);
    cudaGetSymbolAddress((void**)&csr_w, g_csr_w);
    cudaGetSymbolAddress((void**)&srcI, g_src);
    cudaGetSymbolAddress((void**)&dstI, g_dst);

    const int TPB = 256;
    const int gN = (N_NODES + TPB - 1) / TPB;
    const int gE = (N_EDGES + TPB - 1) / TPB;
    const int gGather = (int)(((long long)N_NODES * 32 + TPB - 1) / TPB);
    dim3 gGemm((N_NODES + BM - 1) / BM, D / BN);

    // ---- prep: decode indices, build CSR by destination ----
    detect_idx_kernel<<<1, 32>>>((const unsigned int*)ei);
    convert_idx_kernel<<<gE, TPB>>>(ei, srcI, dstI);
    zero_cnt_kernel<<<gN, TPB>>>(cnt, cursor);
    count_kernel<<<gE, TPB>>>(dstI, cnt);
    scan_kernel<<<1, 1024>>>(cnt, rowstart);
    dinv_kernel<<<gN, TPB>>>(cnt, dinv);
    fill_kernel<<<gE, TPB>>>(srcI, dstI, rowstart, cursor, dinv, csr_src, csr_w);

    // ---- layer 1 ----
    tgemm_kernel<<<gGemm, TPB>>>(x, W1, h, N_NODES);
    gather_kernel<<<gGather, TPB>>>(h, rowstart, csr_src, csr_w, dinv, b1, agg);

    // ---- layer 2 ----
    tgemm_kernel<<<gGemm, TPB>>>(agg, W2, h, N_NODES);
    gather_kernel<<<gGather, TPB>>>(h, rowstart, csr_src, csr_w, dinv, b2, out);
}